// round 6
// baseline (speedup 1.0000x reference)
#include <cuda_runtime.h>
#include <cub/cub.cuh>
#include <cstdint>

// Problem constants (B=8, L=1e6, C=4 -> size=1349)
#define SPIRAL_SIZE 1349
#define HALF        674
#define NCELL       (SPIRAL_SIZE * SPIRAL_SIZE)   // 1,819,801 < 2^21
#define SIGLEN      1000000
#define NBATCH      8

#define PI_F 3.14159274101257324f   // fl(pi)

// Validity cutoff (validated rel_err==0.0): rings 0..564 cover all ranks < 1e6.
#define KMAX   564
#define NRV    (KMAX + 1)
#define BPR    2048                 // buckets per ring
#define NBKT   (NRV * BPR)          // 1,157,120

#define SCAN_BLK   512
#define SCAN_ITEMS 4                // buckets per thread
#define SCAN_TILE  (SCAN_BLK * SCAN_ITEMS)  // 2048 (== BPR)
#define NTILES     (NBKT / SCAN_TILE)       // 565 exact

#define SORTCAP     1100000
#define HALF_ROWS   (HALF + 1)
#define HALF_CELLS  (HALF_ROWS * SPIRAL_SIZE)  // 910,575

#define FLAG_INVALID 0u
#define FLAG_AGG     1u
#define FLAG_PREFIX  2u

__device__ uint32_t           g_hist16[NBKT / 2];   // two u16 counts per word
__device__ uint32_t           g_cursor[NBKT];
__device__ uint32_t           g_kb[NCELL];
__device__ unsigned long long g_sorted[SORTCAP];
__device__ volatile uint32_t  g_status[NTILES];     // (sum << 2) | flag
__device__ uint32_t           g_ticket;

extern "C" __device__ float __nv_atan2f(float, float);

__device__ __forceinline__ uint32_t hist_count(uint32_t b) {
    return (g_hist16[b >> 1] >> ((b & 1u) * 16u)) & 0xFFFFu;
}

// JAX acos: acos(x) = 2*atan2(sqrt(1-x*x), 1+x); exact pi at x==-1.
__device__ __forceinline__ float acos_jax(float xq) {
    if (xq == -1.0f) return PI_F;
    float t  = __fsub_rn(1.0f, __fmul_rn(xq, xq));
    float sq = __fsqrt_rn(t);
    return __fmul_rn(2.0f, __nv_atan2f(sq, __fadd_rn(1.0f, xq)));
}

// Per-ring bucket mapping (inline). Keys of ring k lie in [T-pi, T+pi],
// T = fl(2k*pi); bound +-3.2 guarantees containment. (kb-lo)>>sh < 2048.
__device__ __forceinline__ void ring_map(int k, uint32_t& lo, int& sh) {
    float T   = __fmul_rn((float)(2 * k), PI_F);
    float lof = fmaxf(__fsub_rn(T, 3.2f), 0.0f);
    float hif = __fadd_rn(T, 3.2f);
    lo = __float_as_uint(lof);
    uint32_t span = __float_as_uint(hif) - lo;
    int bn = 32 - __clz(span | 1);
    sh = (bn > 11) ? (bn - 11) : 0;
}

// K0: zero histogram + scan bookkeeping.
__global__ void zero_kernel() {
    int t = blockIdx.x * blockDim.x + threadIdx.x;
    if (t < NBKT / 8) ((uint4*)g_hist16)[t] = make_uint4(0, 0, 0, 0);
    if (t < NTILES) g_status[t] = FLAG_INVALID;
    if (t == 0) g_ticket = 0;
}

// ---------------------------------------------------------------------------
// K1: dense over x2>=0 half-plane; one thread -> key for its cell AND mirror
// (bit-exact: r, xq, A identical; phi*sign(x2) is an exact sign flip).
// ---------------------------------------------------------------------------
__global__ __launch_bounds__(256) void key_kernel() {
    int tid = blockIdx.x * blockDim.x + threadIdx.x;
    if (tid >= HALF_CELLS) return;
    int di = tid / SPIRAL_SIZE;
    int j  = tid - di * SPIRAL_SIZE;
    int i  = HALF + di;

    float x1 = (float)(j - HALF);
    float x2 = (float)di;
    float rr = __fadd_rn(__fmul_rn(x1, x1), __fmul_rn(x2, x2));
    float r  = __fsqrt_rn(rr);
    int   k  = (int)rintf(r);
    if (k > KMAX) return;

    float T = __fmul_rn(__fmul_rn(rintf(r), 2.0f), PI_F);
    uint32_t lo; int sh;
    ring_map(k, lo, sh);
    uint32_t bb = (uint32_t)k * BPR;

    int s = i * SPIRAL_SIZE + j;

    if (di == 0) {
        float phi = (x1 < 0.0f) ? PI_F : 0.0f;   // x2==0 row (NaN-fixed center)
        uint32_t kb = __float_as_uint(__fadd_rn(T, phi));
        g_kb[s] = kb;
        uint32_t b = bb + ((kb - lo) >> sh);
        atomicAdd(&g_hist16[b >> 1], 1u << ((b & 1u) * 16u));
        return;
    }

    float A = acos_jax(__fdiv_rn(x1, r));

    uint32_t kb = __float_as_uint(__fadd_rn(T, A));      // phi = +A
    g_kb[s] = kb;
    uint32_t b = bb + ((kb - lo) >> sh);
    atomicAdd(&g_hist16[b >> 1], 1u << ((b & 1u) * 16u));

    int sm = (2 * HALF - i) * SPIRAL_SIZE + j;
    uint32_t kbm = __float_as_uint(__fadd_rn(T, -A));    // mirror: phi = -A
    g_kb[sm] = kbm;
    uint32_t bm = bb + ((kbm - lo) >> sh);
    atomicAdd(&g_hist16[bm >> 1], 1u << ((bm & 1u) * 16u));
}

// ---------------------------------------------------------------------------
// K2: single-pass exclusive scan hist16 -> g_cursor, decoupled lookback.
// Status word packs payload+flag (single 32-bit write = atomic publication).
// Ticket ordering makes the lookback chain deadlock-free.
// ---------------------------------------------------------------------------
__global__ __launch_bounds__(SCAN_BLK) void scan_kernel() {
    typedef cub::BlockScan<uint32_t, SCAN_BLK> BS;
    __shared__ typename BS::TempStorage tmp;
    __shared__ uint32_t s_tile;
    __shared__ uint32_t s_exclusive;

    if (threadIdx.x == 0) s_tile = atomicAdd(&g_ticket, 1u);
    __syncthreads();
    const uint32_t tile = s_tile;
    const int t = threadIdx.x;

    // Load 4 bucket counts (2 packed words).
    int wbase = (tile * SCAN_TILE + t * SCAN_ITEMS) >> 1;
    uint2 w = ((const uint2*)g_hist16)[wbase >> 1];
    uint32_t c0 = w.x & 0xFFFFu, c1 = w.x >> 16;
    uint32_t c2 = w.y & 0xFFFFu, c3 = w.y >> 16;
    uint32_t sum = c0 + c1 + c2 + c3;

    uint32_t tb, block_total;
    BS(tmp).ExclusiveSum(sum, tb, block_total);

    // Publish aggregate (tile 0 publishes final prefix immediately).
    if (t == 0)
        g_status[tile] = (block_total << 2) |
                         (tile == 0 ? FLAG_PREFIX : FLAG_AGG);

    // Warp 0: parallel lookback.
    if (tile == 0) {
        if (t == 0) s_exclusive = 0;
    } else if (t < 32) {
        uint32_t excl = 0;
        int base = (int)tile;
        for (;;) {
            int idx = base - 32 + t;
            uint32_t st;
            if (idx >= 0) {
                do { st = g_status[idx]; } while ((st & 3u) == FLAG_INVALID);
            } else {
                st = FLAG_PREFIX;            // virtual zero-prefix before tile 0
            }
            uint32_t pmask = __ballot_sync(0xFFFFFFFFu, (st & 3u) == FLAG_PREFIX);
            int hp = 31 - __clz(pmask);      // pmask != 0 guaranteed at idx<0
            uint32_t contrib = (t >= hp) ? (st >> 2) : 0u;
#pragma unroll
            for (int d = 16; d > 0; d >>= 1)
                contrib += __shfl_down_sync(0xFFFFFFFFu, contrib, d);
            contrib = __shfl_sync(0xFFFFFFFFu, contrib, 0);
            excl += contrib;
            if (pmask & 0x80000000u ? true : (hp >= 0 && idx >= 0) ) {
                // a PREFIX was found in this window -> done
            }
            if (pmask) break;
            base -= 32;
        }
        if (t == 0) {
            s_exclusive = excl;
            g_status[tile] = ((excl + block_total) << 2) | FLAG_PREFIX;
        }
    }
    __syncthreads();

    uint32_t run = s_exclusive + tb;
    uint4 o;
    o.x = run; run += c0;
    o.y = run; run += c1;
    o.z = run; run += c2;
    o.w = run;
    ((uint4*)g_cursor)[(tile * SCAN_TILE + t * SCAN_ITEMS) >> 2] = o;
}

// K3: scatter packed (kb<<21 | s) into bucket slots.
__global__ __launch_bounds__(256) void scatter_kernel() {
    int s = blockIdx.x * blockDim.x + threadIdx.x;
    if (s >= NCELL) return;
    int i = s / SPIRAL_SIZE, j = s - i * SPIRAL_SIZE;
    float x1 = (float)(j - HALF), x2 = (float)(i - HALF);
    float r = __fsqrt_rn(__fadd_rn(__fmul_rn(x1, x1), __fmul_rn(x2, x2)));
    int k = (int)rintf(r);
    if (k > KMAX) return;
    uint32_t lo; int sh;
    ring_map(k, lo, sh);
    uint32_t kb = g_kb[s];
    uint32_t b  = (uint32_t)k * BPR + ((kb - lo) >> sh);
    uint32_t pos = atomicAdd(&g_cursor[b], 1u);
    g_sorted[pos] = ((unsigned long long)kb << 21) | (uint32_t)s;
}

// ---------------------------------------------------------------------------
// K4 (fused rank + gather): rank = bucketStart + #{smaller packed peers}
// (index-stable ties == jnp.argsort); bucketStart = cursor[b] - hist[b].
// ---------------------------------------------------------------------------
__global__ __launch_bounds__(256) void gather_kernel(
        const float4* __restrict__ in, float4* __restrict__ out) {
    int s = blockIdx.x * blockDim.x + threadIdx.x;
    if (s >= NCELL) return;
    int i = s / SPIRAL_SIZE, j = s - i * SPIRAL_SIZE;
    float x1 = (float)(j - HALF), x2 = (float)(i - HALF);
    float r = __fsqrt_rn(__fadd_rn(__fmul_rn(x1, x1), __fmul_rn(x2, x2)));
    int k = (int)rintf(r);

    bool valid = (k <= KMAX);
    uint32_t rank = 0xFFFFFFFFu;
    if (valid) {
        uint32_t lo; int sh;
        ring_map(k, lo, sh);
        uint32_t kb  = g_kb[s];
        uint32_t b   = (uint32_t)k * BPR + ((kb - lo) >> sh);
        uint32_t end = g_cursor[b];
        uint32_t cnt = hist_count(b);
        uint32_t st  = end - cnt;
        rank = st;
        if (cnt > 1) {
            unsigned long long my = ((unsigned long long)kb << 21) | (uint32_t)s;
            for (uint32_t q = st; q < end; q++)
                rank += (g_sorted[q] < my) ? 1u : 0u;
        }
        valid = (rank < (uint32_t)SIGLEN);
    }

    float4 z = make_float4(0.0f, 0.0f, 0.0f, 0.0f);
#pragma unroll
    for (int b = 0; b < NBATCH; b++) {
        float4 w = z;
        if (valid) w = __ldg(&in[(size_t)b * SIGLEN + rank]);
        __stcs(&out[(size_t)b * NCELL + s], w);
    }
}

extern "C" void kernel_launch(void* const* d_in, const int* in_sizes, int n_in,
                              void* d_out, int out_size) {
    (void)in_sizes; (void)n_in; (void)out_size;

    zero_kernel<<<(NBKT / 8 + 255) / 256, 256>>>();
    key_kernel<<<(HALF_CELLS + 255) / 256, 256>>>();
    scan_kernel<<<NTILES, SCAN_BLK>>>();

    const int G = (NCELL + 255) / 256;
    scatter_kernel<<<G, 256>>>();
    gather_kernel<<<G, 256>>>((const float4*)d_in[0], (float4*)d_out);
}